// round 9
// baseline (speedup 1.0000x reference)
#include <cuda_runtime.h>

// LoRALayerNorm: x [B=2, S=4096, N=8192] fp32.
// Two kernels overlapped via PDL (programmatic dependent launch):
//   k1 (16 CTAs): rank-4 diag -> g_scale/g_shift, triggers early launch.
//   k2 (8192 CTAs): register-resident single-pass layernorm. The grid-dep
//      sync is hoisted to right after the x loads are ISSUED, so wave-1
//      CTAs overlap the wait on k1 with their own DRAM load latency and
//      the whole reduction tree (instead of stalling the epilogue).

#define N_FEAT 8192
#define N_ROWS 8192
#define RANK 4
#define SCALING_F 2.0f   // ALPHA/RANK = 8/4
#define EPS_F 1e-5f

#define TPB 512
#define VPT 4            // float4 per thread: 512*4*4 = 8192 floats per row

__device__ float g_scale[N_FEAT];
__device__ float g_shift[N_FEAT];

// ---------------------------------------------------------------------------
// Kernel 1: low-rank diagonal -> scale/shift vectors
// ---------------------------------------------------------------------------
__global__ __launch_bounds__(TPB)
void compute_vectors_kernel(const float* __restrict__ sA,
                            const float* __restrict__ sB,
                            const float* __restrict__ hA,
                            const float* __restrict__ hB) {
    // Let the dependent grid begin launching immediately; correctness is
    // guarded by cudaGridDependencySynchronize() in kernel 2.
    cudaTriggerProgrammaticLaunchCompletion();

    int i = blockIdx.x * blockDim.x + threadIdx.x;
    if (i >= N_FEAT) return;
    float4 a_s = __ldg(reinterpret_cast<const float4*>(sA + i * RANK));
    float4 a_h = __ldg(reinterpret_cast<const float4*>(hA + i * RANK));
    float sc = a_s.x * __ldg(&sB[0 * N_FEAT + i])
             + a_s.y * __ldg(&sB[1 * N_FEAT + i])
             + a_s.z * __ldg(&sB[2 * N_FEAT + i])
             + a_s.w * __ldg(&sB[3 * N_FEAT + i]);
    float sh = a_h.x * __ldg(&hB[0 * N_FEAT + i])
             + a_h.y * __ldg(&hB[1 * N_FEAT + i])
             + a_h.z * __ldg(&hB[2 * N_FEAT + i])
             + a_h.w * __ldg(&hB[3 * N_FEAT + i]);
    g_scale[i] = sc * SCALING_F;
    g_shift[i] = sh * SCALING_F;
}

// ---------------------------------------------------------------------------
// Kernel 2: one CTA per row, register-resident single-pass layernorm
// ---------------------------------------------------------------------------
__global__ __launch_bounds__(TPB, 3)
void lora_layernorm_kernel(const float* __restrict__ x,
                           float* __restrict__ out) {
    const int row = blockIdx.x;
    const int tid = threadIdx.x;
    const float4* xrow = reinterpret_cast<const float4*>(x + (size_t)row * N_FEAT);
    float4* orow = reinterpret_cast<float4*>(out + (size_t)row * N_FEAT);

    // Streaming loads of x — issued first, independent of kernel 1.
    float4 v[VPT];
#pragma unroll
    for (int k = 0; k < VPT; k++) {
        v[k] = __ldcs(&xrow[tid + k * TPB]);
    }

    // Wait for kernel 1 while our loads are still in flight: the wait
    // overlaps DRAM latency + the reduction below. No-op for waves >= 2.
    cudaGridDependencySynchronize();

    float sum = 0.0f, sumsq = 0.0f;
#pragma unroll
    for (int k = 0; k < VPT; k++) {
        float4 t = v[k];
        sum += t.x + t.y + t.z + t.w;
        sumsq += t.x * t.x + t.y * t.y + t.z * t.z + t.w * t.w;
    }

#pragma unroll
    for (int off = 16; off > 0; off >>= 1) {
        sum += __shfl_xor_sync(0xffffffffu, sum, off);
        sumsq += __shfl_xor_sync(0xffffffffu, sumsq, off);
    }

    __shared__ float s_sum[TPB / 32];
    __shared__ float s_sumsq[TPB / 32];
    __shared__ float s_mean, s_rstd;
    const int wid = tid >> 5;
    const int lane = tid & 31;
    if (lane == 0) {
        s_sum[wid] = sum;
        s_sumsq[wid] = sumsq;
    }
    __syncthreads();
    if (wid == 0) {
        float a = (lane < TPB / 32) ? s_sum[lane] : 0.0f;
        float b = (lane < TPB / 32) ? s_sumsq[lane] : 0.0f;
#pragma unroll
        for (int off = 8; off > 0; off >>= 1) {
            a += __shfl_xor_sync(0xffffffffu, a, off);
            b += __shfl_xor_sync(0xffffffffu, b, off);
        }
        if (lane == 0) {
            float mean = a * (1.0f / N_FEAT);
            float var = b * (1.0f / N_FEAT) - mean * mean;
            s_mean = mean;
            s_rstd = rsqrtf(var + EPS_F);
        }
    }
    __syncthreads();
    const float mean = s_mean;
    const float rstd = s_rstd;

    const float4* scv = reinterpret_cast<const float4*>(g_scale);
    const float4* shv = reinterpret_cast<const float4*>(g_shift);
#pragma unroll
    for (int k = 0; k < VPT; k++) {
        const int idx = tid + k * TPB;
        float4 sc = __ldg(&scv[idx]);
        float4 sh = __ldg(&shv[idx]);
        float4 t = v[k];
        float4 o;
        o.x = (t.x - mean) * rstd * sc.x + sh.x;
        o.y = (t.y - mean) * rstd * sc.y + sh.y;
        o.z = (t.z - mean) * rstd * sc.z + sh.z;
        o.w = (t.w - mean) * rstd * sc.w + sh.w;
        __stcs(&orow[idx], o);
    }
}

// ---------------------------------------------------------------------------
extern "C" void kernel_launch(void* const* d_in, const int* in_sizes, int n_in,
                              void* d_out, int out_size) {
    const float* x = (const float*)d_in[0];
    const float* sA = (const float*)d_in[1];
    const float* sB = (const float*)d_in[2];
    const float* hA = (const float*)d_in[3];
    const float* hB = (const float*)d_in[4];
    float* out = (float*)d_out;

    compute_vectors_kernel<<<N_FEAT / TPB, TPB>>>(sA, sB, hA, hB);

    cudaLaunchConfig_t cfg = {};
    cfg.gridDim = dim3(N_ROWS, 1, 1);
    cfg.blockDim = dim3(TPB, 1, 1);
    cfg.dynamicSmemBytes = 0;
    cfg.stream = 0;
    cudaLaunchAttribute attr[1];
    attr[0].id = cudaLaunchAttributeProgrammaticStreamSerialization;
    attr[0].val.programmaticStreamSerializationAllowed = 1;
    cfg.attrs = attr;
    cfg.numAttrs = 1;
    cudaLaunchKernelEx(&cfg, lora_layernorm_kernel, x, out);
}